// round 3
// baseline (speedup 1.0000x reference)
#include <cuda_runtime.h>
#include <math.h>

// ---------------------------------------------------------------------------
// Model constants
// ---------------------------------------------------------------------------
#define N_LAYER 4
#define N_HEADS 16
#define C_DIM   1024
#define T_SEQ   1024
#define B_SZ    2
#define ROWS    (B_SZ * T_SEQ)      // 2048
#define F4_DIM  (4 * C_DIM)         // 4096
#define HEAD_D  64
#define VOCABP1 101
#define TRANS   16

// ---------------------------------------------------------------------------
// Static device scratch (no allocations allowed)
// ---------------------------------------------------------------------------
__device__ float g_x [ROWS * C_DIM];   // residual stream
__device__ float g_h [ROWS * C_DIM];   // LN output / attn output scratch
__device__ float g_q [ROWS * C_DIM];
__device__ float g_k [ROWS * C_DIM];
__device__ float g_v [ROWS * C_DIM];
__device__ float g_ff[ROWS * F4_DIM];  // MLP hidden

// ---------------------------------------------------------------------------
// Embedding: x = tok_emb[tokens] + pos_emb
// ---------------------------------------------------------------------------
__global__ void embed_kernel(const int* __restrict__ tokens,
                             const float* __restrict__ tok_emb,
                             const float* __restrict__ pos_emb,
                             float* __restrict__ X)
{
    int i = blockIdx.x * blockDim.x + threadIdx.x;   // over ROWS*C_DIM
    int row = i >> 10;            // /1024
    int c   = i & 1023;
    int t   = row & 1023;         // row = b*1024 + t
    int tok = tokens[row];
    X[i] = tok_emb[(size_t)tok * C_DIM + c] + pos_emb[(size_t)t * C_DIM + c];
}

// ---------------------------------------------------------------------------
// LayerNorm (population variance, eps=1e-5). One block (256 thr) per row.
// ---------------------------------------------------------------------------
__global__ void ln_kernel(const float* __restrict__ X,
                          const float* __restrict__ w,
                          const float* __restrict__ b,
                          float* __restrict__ Y)
{
    const int row = blockIdx.x;
    const float* x = X + (size_t)row * C_DIM;
    float* y       = Y + (size_t)row * C_DIM;
    const int tid = threadIdx.x;

    float v[4];
    float s = 0.f;
#pragma unroll
    for (int i = 0; i < 4; ++i) { v[i] = x[tid + 256 * i]; s += v[i]; }

    __shared__ float red[8];
#pragma unroll
    for (int off = 16; off; off >>= 1) s += __shfl_xor_sync(~0u, s, off);
    if ((tid & 31) == 0) red[tid >> 5] = s;
    __syncthreads();
    float tot = 0.f;
#pragma unroll
    for (int j = 0; j < 8; ++j) tot += red[j];
    const float mu = tot * (1.0f / C_DIM);
    __syncthreads();

    float ss = 0.f;
#pragma unroll
    for (int i = 0; i < 4; ++i) { float d = v[i] - mu; ss += d * d; }
#pragma unroll
    for (int off = 16; off; off >>= 1) ss += __shfl_xor_sync(~0u, ss, off);
    if ((tid & 31) == 0) red[tid >> 5] = ss;
    __syncthreads();
    float tot2 = 0.f;
#pragma unroll
    for (int j = 0; j < 8; ++j) tot2 += red[j];
    const float var = tot2 * (1.0f / C_DIM);
    const float rs  = rsqrtf(var + 1e-5f);

#pragma unroll
    for (int i = 0; i < 4; ++i) {
        int c = tid + 256 * i;
        y[c] = (v[i] - mu) * rs * w[c] + b[c];
    }
}

// ---------------------------------------------------------------------------
// Tiled SGEMM: C[M,N] = A[M,K] @ B[K,N] (+bias) (+residual | gelu)
// BK=8, 256 threads. EPI: 1 = bias, 2 = bias+residual, 3 = bias+gelu(exact)
// ---------------------------------------------------------------------------
template<int BM, int BN, int TM, int TN, int EPI>
__global__ __launch_bounds__(256)
void sgemm_kernel(const float* __restrict__ A, const float* __restrict__ B,
                  const float* __restrict__ bias, const float* __restrict__ R,
                  float* __restrict__ C, int M, int N, int K)
{
    constexpr int BK = 8;
    __shared__ float As[BK][BM];
    __shared__ float Bs[BK][BN];

    const int tid = threadIdx.x;
    const int bx = blockIdx.x, by = blockIdx.y;

    constexpr int TX = BN / TN;            // threads along N
    const int tx = tid % TX;
    const int ty = tid / TX;

    constexpr int CNTA = BM * BK / 256;    // floats per thread (A tile)
    constexpr int TPRA = BK / CNTA;        // threads per A row
    const int rowA = tid / TPRA;
    const int kA   = (tid % TPRA) * CNTA;

    const int rowB = tid / 32;             // BN == 128: float4 per thread
    const int colB = (tid % 32) * 4;

    const float* Aptr = A + (size_t)(by * BM) * K;
    const float* Bptr = B + (size_t)(bx * BN);

    float acc[TM][TN];
#pragma unroll
    for (int i = 0; i < TM; ++i)
#pragma unroll
        for (int j = 0; j < TN; ++j) acc[i][j] = 0.f;

    for (int kt = 0; kt < K; kt += BK) {
#pragma unroll
        for (int j = 0; j < CNTA; ++j)
            As[kA + j][rowA] = Aptr[(size_t)rowA * K + kt + kA + j];
        float4 bv = *reinterpret_cast<const float4*>(Bptr + (size_t)(kt + rowB) * N + colB);
        *reinterpret_cast<float4*>(&Bs[rowB][colB]) = bv;
        __syncthreads();
#pragma unroll
        for (int k = 0; k < BK; ++k) {
            float ar[TM], br[TN];
#pragma unroll
            for (int i = 0; i < TM; ++i) ar[i] = As[k][ty * TM + i];
#pragma unroll
            for (int j = 0; j < TN; ++j) br[j] = Bs[k][tx * TN + j];
#pragma unroll
            for (int i = 0; i < TM; ++i)
#pragma unroll
                for (int j = 0; j < TN; ++j) acc[i][j] += ar[i] * br[j];
        }
        __syncthreads();
    }

#pragma unroll
    for (int i = 0; i < TM; ++i) {
        const int row = by * BM + ty * TM + i;
#pragma unroll
        for (int j = 0; j < TN; ++j) {
            const int col = bx * BN + tx * TN + j;
            float v = acc[i][j] + bias[col];
            if (EPI == 2) v += R[(size_t)row * N + col];
            if (EPI == 3) v = 0.5f * v * (1.0f + erff(v * 0.70710678118654752f));
            C[(size_t)row * N + col] = v;
        }
    }
}

// ---------------------------------------------------------------------------
// Fused masked-causal attention, online softmax.
// grid = (B*H, T/8); block 256 = 8 warps; warp <-> one query row.
// K/V tiles (64 keys x 64 dims) staged in SMEM, shared by the 8 warps.
// Mask: s <= t AND (s % 16 != 15). scale = 1/sqrt(64) = 0.125.
// ---------------------------------------------------------------------------
__global__ __launch_bounds__(256)
void attn_kernel(const float* __restrict__ Q, const float* __restrict__ K,
                 const float* __restrict__ V, float* __restrict__ Y)
{
    const int bh = blockIdx.x;
    const int b  = bh >> 4;
    const int h  = bh & 15;
    const int qbase = blockIdx.y * 8;
    const int warp = threadIdx.x >> 5;
    const int lane = threadIdx.x & 31;
    const int tq = qbase + warp;

    __shared__ float Ks[64][66];
    __shared__ float Vs[64][66];

    const size_t rowq = (size_t)(b * T_SEQ + tq) * C_DIM + h * HEAD_D;
    const float q0 = Q[rowq + lane * 2];
    const float q1 = Q[rowq + lane * 2 + 1];

    float m = -INFINITY, l = 0.f, acc0 = 0.f, acc1 = 0.f;
    const int smax = qbase + 7;

    for (int s0 = 0; s0 <= smax; s0 += 64) {
        const int tile = min(64, smax + 1 - s0);
        __syncthreads();
        for (int idx = threadIdx.x; idx < 64 * 64; idx += 256) {
            const int r = idx >> 6, c = idx & 63;
            float kv = 0.f, vv = 0.f;
            if (r < tile) {
                const size_t g = (size_t)(b * T_SEQ + s0 + r) * C_DIM + h * HEAD_D + c;
                kv = K[g]; vv = V[g];
            }
            Ks[r][c] = kv; Vs[r][c] = vv;
        }
        __syncthreads();

        const int send = min(tq, s0 + 63);
        for (int s = s0; s <= send; ++s) {
            if ((s & 15) == 15) continue;
            const int r = s - s0;
            float p = q0 * Ks[r][lane * 2] + q1 * Ks[r][lane * 2 + 1];
#pragma unroll
            for (int off = 16; off; off >>= 1) p += __shfl_xor_sync(~0u, p, off);
            p *= 0.125f;
            const float mnew = fmaxf(m, p);
            const float corr = __expf(m - mnew);     // 0 when m==-inf
            const float wgt  = __expf(p - mnew);
            l    = l * corr + wgt;
            acc0 = acc0 * corr + wgt * Vs[r][lane * 2];
            acc1 = acc1 * corr + wgt * Vs[r][lane * 2 + 1];
            m = mnew;
        }
    }
    const float inv = 1.0f / l;
    Y[rowq + lane * 2]     = acc0 * inv;
    Y[rowq + lane * 2 + 1] = acc1 * inv;
}

// ---------------------------------------------------------------------------
// EinLinear head: out[r, o] = dot(head_w[r%16, o, :], x[r, :]),  o < 101
// grid = 256 blocks: e = bid%16, chunk = bid/16 -> 8 rows sharing weight reads
// ---------------------------------------------------------------------------
__global__ __launch_bounds__(256)
void head_kernel(const float* __restrict__ X, const float* __restrict__ Wh,
                 float* __restrict__ out)
{
    const int e     = blockIdx.x & 15;
    const int chunk = blockIdx.x >> 4;
    const int tid = threadIdx.x;
    const int warp = tid >> 5, lane = tid & 31;

    __shared__ float xs[8][C_DIM];   // 32 KB
    int rows[8];
#pragma unroll
    for (int j = 0; j < 8; ++j) rows[j] = (chunk * 8 + j) * TRANS + e;

#pragma unroll
    for (int j = 0; j < 8; ++j)
        for (int idx = tid; idx < C_DIM; idx += 256)
            xs[j][idx] = X[(size_t)rows[j] * C_DIM + idx];
    __syncthreads();

    for (int o = warp; o < VOCABP1; o += 8) {
        const float* w = Wh + ((size_t)e * VOCABP1 + o) * C_DIM;
        float a[8];
#pragma unroll
        for (int j = 0; j < 8; ++j) a[j] = 0.f;
        for (int k = lane; k < C_DIM; k += 32) {
            const float wv = w[k];
#pragma unroll
            for (int j = 0; j < 8; ++j) a[j] += wv * xs[j][k];
        }
#pragma unroll
        for (int j = 0; j < 8; ++j)
#pragma unroll
            for (int off = 16; off; off >>= 1)
                a[j] += __shfl_xor_sync(~0u, a[j], off);
        if (lane == 0) {
#pragma unroll
            for (int j = 0; j < 8; ++j)
                out[(size_t)rows[j] * VOCABP1 + o] = a[j];
        }
    }
}

// ---------------------------------------------------------------------------
// Launch
// ---------------------------------------------------------------------------
extern "C" void kernel_launch(void* const* d_in, const int* in_sizes, int n_in,
                              void* d_out, int out_size)
{
    const int*   tokens  = (const int*)  d_in[0];
    const float* tok_emb = (const float*)d_in[1];
    const float* pos_emb = (const float*)d_in[2];
    const float* Wq = (const float*)d_in[3];  const float* bq = (const float*)d_in[4];
    const float* Wk = (const float*)d_in[5];  const float* bk = (const float*)d_in[6];
    const float* Wv = (const float*)d_in[7];  const float* bv = (const float*)d_in[8];
    const float* Wp = (const float*)d_in[9];  const float* bp = (const float*)d_in[10];
    const float* ln1w = (const float*)d_in[11]; const float* ln1b = (const float*)d_in[12];
    const float* ln2w = (const float*)d_in[13]; const float* ln2b = (const float*)d_in[14];
    const float* W1 = (const float*)d_in[15]; const float* b1 = (const float*)d_in[16];
    const float* W2 = (const float*)d_in[17]; const float* b2 = (const float*)d_in[18];
    const float* lnfw = (const float*)d_in[19]; const float* lnfb = (const float*)d_in[20];
    const float* head_w = (const float*)d_in[21];

    float *x, *h, *q, *k, *v, *ff;
    cudaGetSymbolAddress((void**)&x,  g_x);
    cudaGetSymbolAddress((void**)&h,  g_h);
    cudaGetSymbolAddress((void**)&q,  g_q);
    cudaGetSymbolAddress((void**)&k,  g_k);
    cudaGetSymbolAddress((void**)&v,  g_v);
    cudaGetSymbolAddress((void**)&ff, g_ff);

    embed_kernel<<<ROWS * C_DIM / 256, 256>>>(tokens, tok_emb, pos_emb, x);

    const dim3 gN1024(C_DIM / 128, ROWS / 64);   // (8, 32)  for N=1024 GEMMs
    const dim3 gN4096(F4_DIM / 128, ROWS / 128); // (32, 16) for N=4096 GEMM

    for (int i = 0; i < N_LAYER; ++i) {
        const size_t wc = (size_t)i * C_DIM * C_DIM;
        const size_t bc = (size_t)i * C_DIM;
        const size_t w1o = (size_t)i * C_DIM * F4_DIM;
        const size_t b1o = (size_t)i * F4_DIM;

        ln_kernel<<<ROWS, 256>>>(x, ln1w + bc, ln1b + bc, h);

        sgemm_kernel<64,128,4,8,1><<<gN1024, 256>>>(h, Wq + wc, bq + bc, nullptr, q, ROWS, C_DIM, C_DIM);
        sgemm_kernel<64,128,4,8,1><<<gN1024, 256>>>(h, Wk + wc, bk + bc, nullptr, k, ROWS, C_DIM, C_DIM);
        sgemm_kernel<64,128,4,8,1><<<gN1024, 256>>>(h, Wv + wc, bv + bc, nullptr, v, ROWS, C_DIM, C_DIM);

        attn_kernel<<<dim3(B_SZ * N_HEADS, T_SEQ / 8), 256>>>(q, k, v, h);

        sgemm_kernel<64,128,4,8,2><<<gN1024, 256>>>(h, Wp + wc, bp + bc, x, x, ROWS, C_DIM, C_DIM);

        ln_kernel<<<ROWS, 256>>>(x, ln2w + bc, ln2b + bc, h);

        sgemm_kernel<128,128,8,8,3><<<gN4096, 256>>>(h, W1 + w1o, b1 + b1o, nullptr, ff, ROWS, F4_DIM, C_DIM);
        sgemm_kernel<64,128,4,8,2><<<gN1024, 256>>>(ff, W2 + (size_t)i * F4_DIM * C_DIM, b2 + bc, x, x, ROWS, C_DIM, F4_DIM);
    }

    ln_kernel<<<ROWS, 256>>>(x, lnfw, lnfb, h);
    head_kernel<<<256, 256>>>(h, head_w, (float*)d_out);
}

// round 6
// speedup vs baseline: 1.8004x; 1.8004x over previous
#include <cuda_runtime.h>
#include <cuda_bf16.h>
#include <cstdint>
#include <math.h>

// ---------------------------------------------------------------------------
// Model constants
// ---------------------------------------------------------------------------
#define N_LAYER 4
#define N_HEADS 16
#define C_DIM   1024
#define T_SEQ   1024
#define B_SZ    2
#define ROWS    (B_SZ * T_SEQ)      // 2048
#define F4_DIM  (4 * C_DIM)         // 4096
#define HEAD_D  64
#define VOCABP1 101
#define TRANS   16

// ---------------------------------------------------------------------------
// Static device scratch (no allocations allowed)
// ---------------------------------------------------------------------------
__device__ float g_x [ROWS * C_DIM];
__device__ float g_h [ROWS * C_DIM];
__device__ float g_q [ROWS * C_DIM];
__device__ float g_k [ROWS * C_DIM];
__device__ float g_v [ROWS * C_DIM];
__device__ float g_ff[ROWS * F4_DIM];

// bf16 split-expanded operands: act [M, 3K] = [hi|lo|hi]; weight [N, 3K] = [hi|hi|lo]
__device__ __nv_bfloat16 g_aexp[(size_t)ROWS * 3 * F4_DIM];
__device__ __nv_bfloat16 g_wq [(size_t)N_LAYER * C_DIM * 3 * C_DIM];
__device__ __nv_bfloat16 g_wk [(size_t)N_LAYER * C_DIM * 3 * C_DIM];
__device__ __nv_bfloat16 g_wv [(size_t)N_LAYER * C_DIM * 3 * C_DIM];
__device__ __nv_bfloat16 g_wp [(size_t)N_LAYER * C_DIM * 3 * C_DIM];
__device__ __nv_bfloat16 g_w1 [(size_t)N_LAYER * F4_DIM * 3 * C_DIM];
__device__ __nv_bfloat16 g_w2 [(size_t)N_LAYER * C_DIM * 3 * F4_DIM];

// ---------------------------------------------------------------------------
// small PTX helpers (all sm_80-safe; NO tcgen05 — ptxas targets plain sm_103)
// ---------------------------------------------------------------------------
__device__ __forceinline__ uint32_t smem_u32(const void* p) {
    uint32_t a;
    asm("{ .reg .u64 t; cvta.to.shared.u64 t, %1; cvt.u32.u64 %0, t; }" : "=r"(a) : "l"(p));
    return a;
}
__device__ __forceinline__ void cp_async16(uint32_t s, const void* g) {
    asm volatile("cp.async.cg.shared.global [%0], [%1], 16;" :: "r"(s), "l"(g));
}
__device__ __forceinline__ void cp_commit() { asm volatile("cp.async.commit_group;"); }
template<int N> __device__ __forceinline__ void cp_wait() {
    asm volatile("cp.async.wait_group %0;" :: "n"(N));
}
__device__ __forceinline__ void ldsm_x4(uint32_t& r0, uint32_t& r1, uint32_t& r2, uint32_t& r3,
                                        uint32_t addr) {
    asm volatile("ldmatrix.sync.aligned.m8n8.x4.shared.b16 {%0,%1,%2,%3}, [%4];"
                 : "=r"(r0), "=r"(r1), "=r"(r2), "=r"(r3) : "r"(addr));
}
__device__ __forceinline__ void mma16816(float* c, const uint32_t* a, uint32_t b0, uint32_t b1) {
    asm volatile("mma.sync.aligned.m16n8k16.row.col.f32.bf16.bf16.f32 "
                 "{%0,%1,%2,%3}, {%4,%5,%6,%7}, {%8,%9}, {%0,%1,%2,%3};"
                 : "+f"(c[0]), "+f"(c[1]), "+f"(c[2]), "+f"(c[3])
                 : "r"(a[0]), "r"(a[1]), "r"(a[2]), "r"(a[3]), "r"(b0), "r"(b1));
}

// ---------------------------------------------------------------------------
// Embedding
// ---------------------------------------------------------------------------
__global__ void embed_kernel(const int* __restrict__ tokens,
                             const float* __restrict__ tok_emb,
                             const float* __restrict__ pos_emb,
                             float* __restrict__ X)
{
    int i = blockIdx.x * blockDim.x + threadIdx.x;
    int row = i >> 10;
    int c   = i & 1023;
    int t   = row & 1023;
    int tok = tokens[row];
    X[i] = tok_emb[(size_t)tok * C_DIM + c] + pos_emb[(size_t)t * C_DIM + c];
}

// ---------------------------------------------------------------------------
// LayerNorm: one block (256 thr) per row
// ---------------------------------------------------------------------------
__global__ void ln_kernel(const float* __restrict__ X,
                          const float* __restrict__ w,
                          const float* __restrict__ b,
                          float* __restrict__ Y)
{
    const int row = blockIdx.x;
    const float* x = X + (size_t)row * C_DIM;
    float* y       = Y + (size_t)row * C_DIM;
    const int tid = threadIdx.x;

    float v[4];
    float s = 0.f;
#pragma unroll
    for (int i = 0; i < 4; ++i) { v[i] = x[tid + 256 * i]; s += v[i]; }

    __shared__ float red[8];
#pragma unroll
    for (int off = 16; off; off >>= 1) s += __shfl_xor_sync(~0u, s, off);
    if ((tid & 31) == 0) red[tid >> 5] = s;
    __syncthreads();
    float tot = 0.f;
#pragma unroll
    for (int j = 0; j < 8; ++j) tot += red[j];
    const float mu = tot * (1.0f / C_DIM);
    __syncthreads();

    float ss = 0.f;
#pragma unroll
    for (int i = 0; i < 4; ++i) { float d = v[i] - mu; ss += d * d; }
#pragma unroll
    for (int off = 16; off; off >>= 1) ss += __shfl_xor_sync(~0u, ss, off);
    if ((tid & 31) == 0) red[tid >> 5] = ss;
    __syncthreads();
    float tot2 = 0.f;
#pragma unroll
    for (int j = 0; j < 8; ++j) tot2 += red[j];
    const float rs = rsqrtf(tot2 * (1.0f / C_DIM) + 1e-5f);

#pragma unroll
    for (int i = 0; i < 4; ++i) {
        int c = tid + 256 * i;
        y[c] = (v[i] - mu) * rs * w[c] + b[c];
    }
}

// ---------------------------------------------------------------------------
// Split fp32 activation X [M,K] -> bf16 A' [M, 3K] = [hi | lo | hi]
// ---------------------------------------------------------------------------
__global__ void expand_act(const float* __restrict__ X, __nv_bfloat16* __restrict__ out,
                           int kbits)
{
    const int K = 1 << kbits;
    int i = blockIdx.x * blockDim.x + threadIdx.x;
    int m = i >> kbits;
    int k = i & (K - 1);
    float x = X[i];
    __nv_bfloat16 hi = __float2bfloat16(x);
    __nv_bfloat16 lo = __float2bfloat16(x - __bfloat162float(hi));
    size_t base = (size_t)m * 3 * K;
    out[base + k]         = hi;
    out[base + K + k]     = lo;
    out[base + 2 * K + k] = hi;
}

// ---------------------------------------------------------------------------
// Split+transpose weight W [K,N] -> bf16 B' [N, 3K] = [hi | hi | lo]
// ---------------------------------------------------------------------------
__global__ void expand_wT(const float* __restrict__ W, __nv_bfloat16* __restrict__ out,
                          int K, int N)
{
    __shared__ float t[32][33];
    const int k0 = blockIdx.x * 32, n0 = blockIdx.y * 32;
    const int tx = threadIdx.x, ty = threadIdx.y;   // 32 x 8
#pragma unroll
    for (int i = 0; i < 4; ++i)
        t[ty + 8 * i][tx] = W[(size_t)(k0 + ty + 8 * i) * N + n0 + tx];
    __syncthreads();
#pragma unroll
    for (int i = 0; i < 4; ++i) {
        int n = n0 + ty + 8 * i;
        int k = k0 + tx;
        float x = t[tx][ty + 8 * i];
        __nv_bfloat16 hi = __float2bfloat16(x);
        __nv_bfloat16 lo = __float2bfloat16(x - __bfloat162float(hi));
        size_t base = (size_t)n * 3 * K;
        out[base + k]         = hi;
        out[base + K + k]     = hi;
        out[base + 2 * K + k] = lo;
    }
}

// ---------------------------------------------------------------------------
// HMMA bf16 GEMM: C[M,N] = A'[M,K3] @ B'[N,K3]^T, fp32 accumulate.
// Tile 128x128, BK=32 bf16, 8 warps (2Mx4N), m16n8k16 atoms, cp.async 3-stage.
// SMEM rows padded to 80B (conflict-free ldmatrix). EPI: 1=bias, 2=+res, 3=+gelu.
// ---------------------------------------------------------------------------
#define GEMM_STAGES 3
#define GEMM_ABYTES (128 * 80)           // one operand tile (padded)
#define GEMM_STAGEB (2 * GEMM_ABYTES)    // A + B
#define GEMM_SMEM   (GEMM_STAGES * GEMM_STAGEB)  // 61440

template<int EPI>
__global__ __launch_bounds__(256)
void mma_gemm(const __nv_bfloat16* __restrict__ A, const __nv_bfloat16* __restrict__ B,
              const float* __restrict__ bias, const float* __restrict__ R,
              float* __restrict__ C, int N, int K3)
{
    extern __shared__ char smem[];
    const uint32_t sbase = smem_u32(smem);
    const int tid  = threadIdx.x;
    const int wid  = tid >> 5, lane = tid & 31;
    const int warp_m = wid >> 2, warp_n = wid & 3;
    const int bx = blockIdx.x, by = blockIdx.y;

    const char* Abase = (const char*)(A + (size_t)(by * 128) * K3);
    const char* Bbase = (const char*)(B + (size_t)(bx * 128) * K3);
    const size_t ldg = (size_t)K3 * 2;

    const int rowc0 = (tid) >> 2,       segc0 = (tid) & 3;
    const int rowc1 = (tid + 256) >> 2, segc1 = (tid + 256) & 3;

    const int nchunks = K3 >> 5;

    // prologue: stage chunks 0..S-2
#pragma unroll
    for (int s = 0; s < GEMM_STAGES - 1; ++s) {
        const uint32_t sb = sbase + s * GEMM_STAGEB;
        cp_async16(sb + rowc0 * 80 + segc0 * 16, Abase + (size_t)rowc0 * ldg + s * 64 + segc0 * 16);
        cp_async16(sb + GEMM_ABYTES + rowc0 * 80 + segc0 * 16, Bbase + (size_t)rowc0 * ldg + s * 64 + segc0 * 16);
        cp_async16(sb + rowc1 * 80 + segc1 * 16, Abase + (size_t)rowc1 * ldg + s * 64 + segc1 * 16);
        cp_async16(sb + GEMM_ABYTES + rowc1 * 80 + segc1 * 16, Bbase + (size_t)rowc1 * ldg + s * 64 + segc1 * 16);
        cp_commit();
    }

    float acc[4][4][4];
#pragma unroll
    for (int i = 0; i < 4; ++i)
#pragma unroll
        for (int j = 0; j < 4; ++j)
#pragma unroll
            for (int r = 0; r < 4; ++r) acc[i][j][r] = 0.f;

    // per-lane ldmatrix base offsets (within a stage buffer)
    const uint32_t a_lm = (uint32_t)((warp_m * 64 + (lane & 15)) * 80 + (lane >> 4) * 16);
    const uint32_t b_lm = (uint32_t)(GEMM_ABYTES +
                           (warp_n * 32 + (lane & 7) + ((lane >> 4) << 3)) * 80 +
                           ((lane >> 3) & 1) * 16);

    for (int c = 0; c < nchunks; ++c) {
        cp_wait<GEMM_STAGES - 2>();
        __syncthreads();

        const uint32_t sb = sbase + (c % GEMM_STAGES) * GEMM_STAGEB;
#pragma unroll
        for (int ks = 0; ks < 2; ++ks) {
            uint32_t af[4][4], bf[2][4];
#pragma unroll
            for (int ma = 0; ma < 4; ++ma)
                ldsm_x4(af[ma][0], af[ma][1], af[ma][2], af[ma][3],
                        sb + a_lm + ma * (16 * 80) + ks * 32);
#pragma unroll
            for (int j = 0; j < 2; ++j)
                ldsm_x4(bf[j][0], bf[j][1], bf[j][2], bf[j][3],
                        sb + b_lm + j * (16 * 80) + ks * 32);
#pragma unroll
            for (int ma = 0; ma < 4; ++ma)
#pragma unroll
                for (int na = 0; na < 4; ++na)
                    mma16816(acc[ma][na], af[ma], bf[na >> 1][(na & 1) * 2],
                             bf[na >> 1][(na & 1) * 2 + 1]);
        }
        __syncthreads();

        const int nc = c + GEMM_STAGES - 1;
        if (nc < nchunks) {
            const uint32_t nb = sbase + (nc % GEMM_STAGES) * GEMM_STAGEB;
            cp_async16(nb + rowc0 * 80 + segc0 * 16, Abase + (size_t)rowc0 * ldg + nc * 64 + segc0 * 16);
            cp_async16(nb + GEMM_ABYTES + rowc0 * 80 + segc0 * 16, Bbase + (size_t)rowc0 * ldg + nc * 64 + segc0 * 16);
            cp_async16(nb + rowc1 * 80 + segc1 * 16, Abase + (size_t)rowc1 * ldg + nc * 64 + segc1 * 16);
            cp_async16(nb + GEMM_ABYTES + rowc1 * 80 + segc1 * 16, Bbase + (size_t)rowc1 * ldg + nc * 64 + segc1 * 16);
            cp_commit();
        }
    }

    // epilogue
#pragma unroll
    for (int ma = 0; ma < 4; ++ma) {
        const int row0 = by * 128 + warp_m * 64 + ma * 16 + (lane >> 2);
        const int row1 = row0 + 8;
#pragma unroll
        for (int na = 0; na < 4; ++na) {
            const int col = bx * 128 + warp_n * 32 + na * 8 + (lane & 3) * 2;
            float v0 = acc[ma][na][0] + bias[col];
            float v1 = acc[ma][na][1] + bias[col + 1];
            float v2 = acc[ma][na][2] + bias[col];
            float v3 = acc[ma][na][3] + bias[col + 1];
            if (EPI == 2) {
                v0 += R[(size_t)row0 * N + col];     v1 += R[(size_t)row0 * N + col + 1];
                v2 += R[(size_t)row1 * N + col];     v3 += R[(size_t)row1 * N + col + 1];
            }
            if (EPI == 3) {
                v0 = 0.5f * v0 * (1.0f + erff(v0 * 0.70710678118654752f));
                v1 = 0.5f * v1 * (1.0f + erff(v1 * 0.70710678118654752f));
                v2 = 0.5f * v2 * (1.0f + erff(v2 * 0.70710678118654752f));
                v3 = 0.5f * v3 * (1.0f + erff(v3 * 0.70710678118654752f));
            }
            *reinterpret_cast<float2*>(C + (size_t)row0 * N + col) = make_float2(v0, v1);
            *reinterpret_cast<float2*>(C + (size_t)row1 * N + col) = make_float2(v2, v3);
        }
    }
}

// ---------------------------------------------------------------------------
// Fused masked-causal attention (fp32, online softmax)
// ---------------------------------------------------------------------------
__global__ __launch_bounds__(256)
void attn_kernel(const float* __restrict__ Q, const float* __restrict__ K,
                 const float* __restrict__ V, float* __restrict__ Y)
{
    const int bh = blockIdx.x;
    const int b  = bh >> 4;
    const int h  = bh & 15;
    const int qbase = blockIdx.y * 8;
    const int warp = threadIdx.x >> 5;
    const int lane = threadIdx.x & 31;
    const int tq = qbase + warp;

    __shared__ float Ks[64][66];
    __shared__ float Vs[64][66];

    const size_t rowq = (size_t)(b * T_SEQ + tq) * C_DIM + h * HEAD_D;
    const float q0 = Q[rowq + lane * 2];
    const float q1 = Q[rowq + lane * 2 + 1];

    float m = -INFINITY, l = 0.f, acc0 = 0.f, acc1 = 0.f;
    const int smax = qbase + 7;

    for (int s0 = 0; s0 <= smax; s0 += 64) {
        const int tile = min(64, smax + 1 - s0);
        __syncthreads();
        for (int idx = threadIdx.x; idx < 64 * 64; idx += 256) {
            const int r = idx >> 6, cc = idx & 63;
            float kv = 0.f, vv = 0.f;
            if (r < tile) {
                const size_t g = (size_t)(b * T_SEQ + s0 + r) * C_DIM + h * HEAD_D + cc;
                kv = K[g]; vv = V[g];
            }
            Ks[r][cc] = kv; Vs[r][cc] = vv;
        }
        __syncthreads();

        const int send = min(tq, s0 + 63);
        for (int s = s0; s <= send; ++s) {
            if ((s & 15) == 15) continue;
            const int r = s - s0;
            float p = q0 * Ks[r][lane * 2] + q1 * Ks[r][lane * 2 + 1];
#pragma unroll
            for (int off = 16; off; off >>= 1) p += __shfl_xor_sync(~0u, p, off);
            p *= 0.125f;
            const float mnew = fmaxf(m, p);
            const float corr = __expf(m - mnew);
            const float wgt  = __expf(p - mnew);
            l    = l * corr + wgt;
            acc0 = acc0 * corr + wgt * Vs[r][lane * 2];
            acc1 = acc1 * corr + wgt * Vs[r][lane * 2 + 1];
            m = mnew;
        }
    }
    const float inv = 1.0f / l;
    Y[rowq + lane * 2]     = acc0 * inv;
    Y[rowq + lane * 2 + 1] = acc1 * inv;
}

// ---------------------------------------------------------------------------
// EinLinear head
// ---------------------------------------------------------------------------
__global__ __launch_bounds__(256)
void head_kernel(const float* __restrict__ X, const float* __restrict__ Wh,
                 float* __restrict__ out)
{
    const int e     = blockIdx.x & 15;
    const int chunk = blockIdx.x >> 4;
    const int tid = threadIdx.x;
    const int warp = tid >> 5, lane = tid & 31;

    __shared__ float xs[8][C_DIM];
    int rows[8];
#pragma unroll
    for (int j = 0; j < 8; ++j) rows[j] = (chunk * 8 + j) * TRANS + e;

#pragma unroll
    for (int j = 0; j < 8; ++j)
        for (int idx = tid; idx < C_DIM; idx += 256)
            xs[j][idx] = X[(size_t)rows[j] * C_DIM + idx];
    __syncthreads();

    for (int o = warp; o < VOCABP1; o += 8) {
        const float* w = Wh + ((size_t)e * VOCABP1 + o) * C_DIM;
        float a[8];
#pragma unroll
        for (int j = 0; j < 8; ++j) a[j] = 0.f;
        for (int k = lane; k < C_DIM; k += 32) {
            const float wv = w[k];
#pragma unroll
            for (int j = 0; j < 8; ++j) a[j] += wv * xs[j][k];
        }
#pragma unroll
        for (int j = 0; j < 8; ++j)
#pragma unroll
            for (int off = 16; off; off >>= 1)
                a[j] += __shfl_xor_sync(~0u, a[j], off);
        if (lane == 0) {
#pragma unroll
            for (int j = 0; j < 8; ++j)
                out[(size_t)rows[j] * VOCABP1 + o] = a[j];
        }
    }
}

// ---------------------------------------------------------------------------
// Launch
// ---------------------------------------------------------------------------
extern "C" void kernel_launch(void* const* d_in, const int* in_sizes, int n_in,
                              void* d_out, int out_size)
{
    const int*   tokens  = (const int*)  d_in[0];
    const float* tok_emb = (const float*)d_in[1];
    const float* pos_emb = (const float*)d_in[2];
    const float* Wq = (const float*)d_in[3];  const float* bq = (const float*)d_in[4];
    const float* Wk = (const float*)d_in[5];  const float* bk = (const float*)d_in[6];
    const float* Wv = (const float*)d_in[7];  const float* bv = (const float*)d_in[8];
    const float* Wp = (const float*)d_in[9];  const float* bp = (const float*)d_in[10];
    const float* ln1w = (const float*)d_in[11]; const float* ln1b = (const float*)d_in[12];
    const float* ln2w = (const float*)d_in[13]; const float* ln2b = (const float*)d_in[14];
    const float* W1 = (const float*)d_in[15]; const float* b1 = (const float*)d_in[16];
    const float* W2 = (const float*)d_in[17]; const float* b2 = (const float*)d_in[18];
    const float* lnfw = (const float*)d_in[19]; const float* lnfb = (const float*)d_in[20];
    const float* head_w = (const float*)d_in[21];

    float *x, *h, *q, *k, *v, *ff;
    __nv_bfloat16 *ax, *wqx, *wkx, *wvx, *wpx, *w1x, *w2x;
    cudaGetSymbolAddress((void**)&x,  g_x);
    cudaGetSymbolAddress((void**)&h,  g_h);
    cudaGetSymbolAddress((void**)&q,  g_q);
    cudaGetSymbolAddress((void**)&k,  g_k);
    cudaGetSymbolAddress((void**)&v,  g_v);
    cudaGetSymbolAddress((void**)&ff, g_ff);
    cudaGetSymbolAddress((void**)&ax,  g_aexp);
    cudaGetSymbolAddress((void**)&wqx, g_wq);
    cudaGetSymbolAddress((void**)&wkx, g_wk);
    cudaGetSymbolAddress((void**)&wvx, g_wv);
    cudaGetSymbolAddress((void**)&wpx, g_wp);
    cudaGetSymbolAddress((void**)&w1x, g_w1);
    cudaGetSymbolAddress((void**)&w2x, g_w2);

    cudaFuncSetAttribute(mma_gemm<1>, cudaFuncAttributeMaxDynamicSharedMemorySize, GEMM_SMEM);
    cudaFuncSetAttribute(mma_gemm<2>, cudaFuncAttributeMaxDynamicSharedMemorySize, GEMM_SMEM);
    cudaFuncSetAttribute(mma_gemm<3>, cudaFuncAttributeMaxDynamicSharedMemorySize, GEMM_SMEM);

    // ---- weight expansion ----
    const dim3 wb(32, 8);
    for (int i = 0; i < N_LAYER; ++i) {
        const size_t wc  = (size_t)i * C_DIM * C_DIM;
        const size_t ec  = (size_t)i * C_DIM * 3 * C_DIM;
        expand_wT<<<dim3(32, 32), wb>>>(Wq + wc, wqx + ec, C_DIM, C_DIM);
        expand_wT<<<dim3(32, 32), wb>>>(Wk + wc, wkx + ec, C_DIM, C_DIM);
        expand_wT<<<dim3(32, 32), wb>>>(Wv + wc, wvx + ec, C_DIM, C_DIM);
        expand_wT<<<dim3(32, 32), wb>>>(Wp + wc, wpx + ec, C_DIM, C_DIM);
        expand_wT<<<dim3(32, 128), wb>>>(W1 + (size_t)i * C_DIM * F4_DIM,
                                         w1x + (size_t)i * F4_DIM * 3 * C_DIM, C_DIM, F4_DIM);
        expand_wT<<<dim3(128, 32), wb>>>(W2 + (size_t)i * F4_DIM * C_DIM,
                                         w2x + (size_t)i * C_DIM * 3 * F4_DIM, F4_DIM, C_DIM);
    }

    embed_kernel<<<ROWS * C_DIM / 256, 256>>>(tokens, tok_emb, pos_emb, x);

    const dim3 gC (C_DIM  / 128, ROWS / 128);   // (8, 16)
    const dim3 gF4(F4_DIM / 128, ROWS / 128);   // (32, 16)
    const int  eaC  = ROWS * C_DIM  / 256;
    const int  eaF4 = ROWS * F4_DIM / 256;

    for (int i = 0; i < N_LAYER; ++i) {
        const size_t bc  = (size_t)i * C_DIM;
        const size_t ec  = (size_t)i * C_DIM * 3 * C_DIM;
        const size_t e1  = (size_t)i * F4_DIM * 3 * C_DIM;
        const size_t e2  = (size_t)i * C_DIM * 3 * F4_DIM;
        const size_t b1o = (size_t)i * F4_DIM;

        ln_kernel<<<ROWS, 256>>>(x, ln1w + bc, ln1b + bc, h);
        expand_act<<<eaC, 256>>>(h, ax, 10);
        mma_gemm<1><<<gC, 256, GEMM_SMEM>>>(ax, wqx + ec, bq + bc, nullptr, q, C_DIM, 3 * C_DIM);
        mma_gemm<1><<<gC, 256, GEMM_SMEM>>>(ax, wkx + ec, bk + bc, nullptr, k, C_DIM, 3 * C_DIM);
        mma_gemm<1><<<gC, 256, GEMM_SMEM>>>(ax, wvx + ec, bv + bc, nullptr, v, C_DIM, 3 * C_DIM);

        attn_kernel<<<dim3(B_SZ * N_HEADS, T_SEQ / 8), 256>>>(q, k, v, h);

        expand_act<<<eaC, 256>>>(h, ax, 10);
        mma_gemm<2><<<gC, 256, GEMM_SMEM>>>(ax, wpx + ec, bp + bc, x, x, C_DIM, 3 * C_DIM);

        ln_kernel<<<ROWS, 256>>>(x, ln2w + bc, ln2b + bc, h);
        expand_act<<<eaC, 256>>>(h, ax, 10);
        mma_gemm<3><<<gF4, 256, GEMM_SMEM>>>(ax, w1x + e1, b1 + b1o, nullptr, ff, F4_DIM, 3 * C_DIM);

        expand_act<<<eaF4, 256>>>(ff, ax, 12);
        mma_gemm<2><<<gC, 256, GEMM_SMEM>>>(ax, w2x + e2, b2 + bc, x, x, C_DIM, 3 * F4_DIM);
    }

    ln_kernel<<<ROWS, 256>>>(x, lnfw, lnfb, h);
    head_kernel<<<256, 256>>>(h, head_w, (float*)d_out);
}

// round 7
// speedup vs baseline: 2.1567x; 1.1979x over previous
#include <cuda_runtime.h>
#include <cuda_bf16.h>
#include <cstdint>
#include <math.h>

// ---------------------------------------------------------------------------
// Model constants
// ---------------------------------------------------------------------------
#define N_LAYER 4
#define N_HEADS 16
#define C_DIM   1024
#define T_SEQ   1024
#define B_SZ    2
#define ROWS    (B_SZ * T_SEQ)      // 2048
#define F4_DIM  (4 * C_DIM)         // 4096
#define HEAD_D  64
#define VOCABP1 101
#define TRANS   16
#define K3C     (3 * C_DIM)         // 3072
#define K3F     (3 * F4_DIM)        // 12288
#define NQKV    (3 * C_DIM)         // 3072

// ---------------------------------------------------------------------------
// Static device scratch (no allocations allowed)
// ---------------------------------------------------------------------------
__device__ float g_x  [ROWS * C_DIM];            // residual stream (fp32)
__device__ float g_h  [ROWS * C_DIM];            // final-LN output (fp32)
__device__ float g_qkv[ROWS * NQKV];             // fused q|k|v (fp32)

__device__ __nv_bfloat16 g_aexpC[(size_t)ROWS * K3C];   // [M, 3C] activation operand
__device__ __nv_bfloat16 g_aexpF[(size_t)ROWS * K3F];   // [M, 3F4] W2 input operand

__device__ __nv_bfloat16 g_wqkv[(size_t)N_LAYER * NQKV * K3C];  // [3072, 3072]/layer
__device__ __nv_bfloat16 g_wp  [(size_t)N_LAYER * C_DIM * K3C];
__device__ __nv_bfloat16 g_w1  [(size_t)N_LAYER * F4_DIM * K3C];
__device__ __nv_bfloat16 g_w2  [(size_t)N_LAYER * C_DIM * K3F];
__device__ float         g_bqkv[N_LAYER * NQKV];

// ---------------------------------------------------------------------------
// PTX helpers (sm_80-safe only; ptxas targets plain sm_103)
// ---------------------------------------------------------------------------
__device__ __forceinline__ uint32_t smem_u32(const void* p) {
    uint32_t a;
    asm("{ .reg .u64 t; cvta.to.shared.u64 t, %1; cvt.u32.u64 %0, t; }" : "=r"(a) : "l"(p));
    return a;
}
__device__ __forceinline__ void cp_async16(uint32_t s, const void* g) {
    asm volatile("cp.async.cg.shared.global [%0], [%1], 16;" :: "r"(s), "l"(g));
}
__device__ __forceinline__ void cp_commit() { asm volatile("cp.async.commit_group;"); }
template<int N> __device__ __forceinline__ void cp_wait() {
    asm volatile("cp.async.wait_group %0;" :: "n"(N));
}
__device__ __forceinline__ void ldsm_x4(uint32_t& r0, uint32_t& r1, uint32_t& r2, uint32_t& r3,
                                        uint32_t addr) {
    asm volatile("ldmatrix.sync.aligned.m8n8.x4.shared.b16 {%0,%1,%2,%3}, [%4];"
                 : "=r"(r0), "=r"(r1), "=r"(r2), "=r"(r3) : "r"(addr));
}
__device__ __forceinline__ void mma16816(float* c, const uint32_t* a, uint32_t b0, uint32_t b1) {
    asm volatile("mma.sync.aligned.m16n8k16.row.col.f32.bf16.bf16.f32 "
                 "{%0,%1,%2,%3}, {%4,%5,%6,%7}, {%8,%9}, {%0,%1,%2,%3};"
                 : "+f"(c[0]), "+f"(c[1]), "+f"(c[2]), "+f"(c[3])
                 : "r"(a[0]), "r"(a[1]), "r"(a[2]), "r"(a[3]), "r"(b0), "r"(b1));
}

// XOR swizzle: row of 128B, 16B segment s8 in 0..7 -> byte offset within tile
__device__ __forceinline__ uint32_t swz(int r, int s8) {
    return (uint32_t)(r * 128 + ((s8 ^ (r & 7)) << 4));
}

// ---------------------------------------------------------------------------
// Embedding
// ---------------------------------------------------------------------------
__global__ void embed_kernel(const int* __restrict__ tokens,
                             const float* __restrict__ tok_emb,
                             const float* __restrict__ pos_emb,
                             float* __restrict__ X)
{
    int i = blockIdx.x * blockDim.x + threadIdx.x;
    int row = i >> 10;
    int c   = i & 1023;
    int t   = row & 1023;
    int tok = tokens[row];
    X[i] = tok_emb[(size_t)tok * C_DIM + c] + pos_emb[(size_t)t * C_DIM + c];
}

// ---------------------------------------------------------------------------
// bias concat for fused QKV
// ---------------------------------------------------------------------------
__global__ void bqkv_kernel(const float* __restrict__ bq, const float* __restrict__ bk,
                            const float* __restrict__ bv, float* __restrict__ out)
{
    int i = blockIdx.x * blockDim.x + threadIdx.x;   // N_LAYER*3072
    int l = i / NQKV;
    int c = i - l * NQKV;
    float v;
    if (c < C_DIM)            v = bq[l * C_DIM + c];
    else if (c < 2 * C_DIM)   v = bk[l * C_DIM + c - C_DIM];
    else                      v = bv[l * C_DIM + c - 2 * C_DIM];
    out[i] = v;
}

// ---------------------------------------------------------------------------
// LayerNorm. EXP=0: write fp32 Y. EXP=1: write bf16 [hi|lo|hi] into Ye [row][3C]
// ---------------------------------------------------------------------------
template<int EXP>
__global__ void ln_kernel(const float* __restrict__ X,
                          const float* __restrict__ w,
                          const float* __restrict__ b,
                          float* __restrict__ Y, __nv_bfloat16* __restrict__ Ye)
{
    const int row = blockIdx.x;
    const float* x = X + (size_t)row * C_DIM;
    const int tid = threadIdx.x;

    float v[4];
    float s = 0.f;
#pragma unroll
    for (int i = 0; i < 4; ++i) { v[i] = x[tid + 256 * i]; s += v[i]; }

    __shared__ float red[8];
#pragma unroll
    for (int off = 16; off; off >>= 1) s += __shfl_xor_sync(~0u, s, off);
    if ((tid & 31) == 0) red[tid >> 5] = s;
    __syncthreads();
    float tot = 0.f;
#pragma unroll
    for (int j = 0; j < 8; ++j) tot += red[j];
    const float mu = tot * (1.0f / C_DIM);
    __syncthreads();

    float ss = 0.f;
#pragma unroll
    for (int i = 0; i < 4; ++i) { float d = v[i] - mu; ss += d * d; }
#pragma unroll
    for (int off = 16; off; off >>= 1) ss += __shfl_xor_sync(~0u, ss, off);
    if ((tid & 31) == 0) red[tid >> 5] = ss;
    __syncthreads();
    float tot2 = 0.f;
#pragma unroll
    for (int j = 0; j < 8; ++j) tot2 += red[j];
    const float rs = rsqrtf(tot2 * (1.0f / C_DIM) + 1e-5f);

#pragma unroll
    for (int i = 0; i < 4; ++i) {
        const int c = tid + 256 * i;
        const float o = (v[i] - mu) * rs * w[c] + b[c];
        if (EXP == 0) {
            Y[(size_t)row * C_DIM + c] = o;
        } else {
            __nv_bfloat16 hi = __float2bfloat16(o);
            __nv_bfloat16 lo = __float2bfloat16(o - __bfloat162float(hi));
            __nv_bfloat16* yr = Ye + (size_t)row * K3C;
            yr[c]             = hi;
            yr[C_DIM + c]     = lo;
            yr[2 * C_DIM + c] = hi;
        }
    }
}

// ---------------------------------------------------------------------------
// Split+transpose weight W [K,N] -> bf16 B' [N, 3K] = [hi | hi | lo]
// ---------------------------------------------------------------------------
__global__ void expand_wT(const float* __restrict__ W, __nv_bfloat16* __restrict__ out,
                          int K, int N)
{
    __shared__ float t[32][33];
    const int k0 = blockIdx.x * 32, n0 = blockIdx.y * 32;
    const int tx = threadIdx.x, ty = threadIdx.y;   // 32 x 8
#pragma unroll
    for (int i = 0; i < 4; ++i)
        t[ty + 8 * i][tx] = W[(size_t)(k0 + ty + 8 * i) * N + n0 + tx];
    __syncthreads();
#pragma unroll
    for (int i = 0; i < 4; ++i) {
        int n = n0 + ty + 8 * i;
        int k = k0 + tx;
        float x = t[tx][ty + 8 * i];
        __nv_bfloat16 hi = __float2bfloat16(x);
        __nv_bfloat16 lo = __float2bfloat16(x - __bfloat162float(hi));
        size_t base = (size_t)n * 3 * K;
        out[base + k]         = hi;
        out[base + K + k]     = hi;
        out[base + 2 * K + k] = lo;
    }
}

// ---------------------------------------------------------------------------
// HMMA bf16 GEMM v2: C[M,N] = A'[M,K3] @ B'[N,K3]^T, fp32 accumulate.
// 128x128 tile, BK=64, 8 warps (2Mx4N), 3-stage cp.async, single sync/chunk.
// 128B rows with XOR-16B swizzle (conflict-free ldmatrix & stores).
// EPI: 1 = bias -> Cf;  2 = bias + residual -> Cf;
//      3 = bias + gelu -> expanded bf16 [hi|lo|hi] into Ce [row][3N]
// ---------------------------------------------------------------------------
#define G_STAGES 3
#define G_TILEB  (128 * 128)            // bytes per operand tile
#define G_STAGEB (2 * G_TILEB)          // A + B
#define G_SMEM   (G_STAGES * G_STAGEB)  // 98304

template<int EPI>
__global__ __launch_bounds__(256)
void mma_gemm(const __nv_bfloat16* __restrict__ A, const __nv_bfloat16* __restrict__ B,
              const float* __restrict__ bias, const float* __restrict__ R,
              float* __restrict__ Cf, __nv_bfloat16* __restrict__ Ce,
              int N, int K3)
{
    extern __shared__ char smem[];
    const uint32_t sbase = smem_u32(smem);
    const int tid  = threadIdx.x;
    const int wid  = tid >> 5, lane = tid & 31;
    const int warp_m = wid >> 2, warp_n = wid & 3;
    const int bx = blockIdx.x, by = blockIdx.y;

    const char* Abase = (const char*)(A + (size_t)(by * 128) * K3);
    const char* Bbase = (const char*)(B + (size_t)(bx * 128) * K3);
    const size_t ldg = (size_t)K3 * 2;
    const int nchunks = K3 >> 6;

    // cp.async mapping: 1024 16B segs per operand tile; 4 per thread
    const int r_cp[4]  = { tid >> 3, (tid + 256) >> 3, (tid + 512) >> 3, (tid + 768) >> 3 };
    const int s_cp[4]  = { tid & 7,  tid & 7,          tid & 7,          tid & 7 };

    // prologue: stages 0,1
#pragma unroll
    for (int st = 0; st < G_STAGES - 1; ++st) {
        const uint32_t sb = sbase + st * G_STAGEB;
#pragma unroll
        for (int p = 0; p < 4; ++p) {
            const int r = r_cp[p], s8 = s_cp[p];
            cp_async16(sb + swz(r, s8),           Abase + (size_t)r * ldg + st * 128 + s8 * 16);
            cp_async16(sb + G_TILEB + swz(r, s8), Bbase + (size_t)r * ldg + st * 128 + s8 * 16);
        }
        cp_commit();
    }

    float acc[4][4][4];
#pragma unroll
    for (int i = 0; i < 4; ++i)
#pragma unroll
        for (int j = 0; j < 4; ++j)
#pragma unroll
            for (int r = 0; r < 4; ++r) acc[i][j][r] = 0.f;

    const int a_r0 = warp_m * 64 + (lane & 15);       // + ma*16
    const int a_s0 = lane >> 4;                        // + ks*2
    const int b_r0 = warp_n * 32 + (lane & 7) + ((lane >> 4) << 3);  // + j*16
    const int b_s0 = (lane >> 3) & 1;                  // + ks*2

    for (int c = 0; c < nchunks; ++c) {
        cp_wait<G_STAGES - 2>();
        __syncthreads();

        // issue loads for chunk c+2 (buffer free since its last readers
        // finished chunk c-1 before the sync above)
        const int nc = c + G_STAGES - 1;
        if (nc < nchunks) {
            const uint32_t nb = sbase + (nc % G_STAGES) * G_STAGEB;
#pragma unroll
            for (int p = 0; p < 4; ++p) {
                const int r = r_cp[p], s8 = s_cp[p];
                cp_async16(nb + swz(r, s8),           Abase + (size_t)r * ldg + nc * 128 + s8 * 16);
                cp_async16(nb + G_TILEB + swz(r, s8), Bbase + (size_t)r * ldg + nc * 128 + s8 * 16);
            }
        }
        cp_commit();

        const uint32_t sb = sbase + (c % G_STAGES) * G_STAGEB;
#pragma unroll
        for (int ks = 0; ks < 4; ++ks) {
            uint32_t af[4][4], bf[2][4];
#pragma unroll
            for (int ma = 0; ma < 4; ++ma) {
                const int r = a_r0 + ma * 16;
                ldsm_x4(af[ma][0], af[ma][1], af[ma][2], af[ma][3],
                        sb + swz(r, ks * 2 + a_s0));
            }
#pragma unroll
            for (int j = 0; j < 2; ++j) {
                const int r = b_r0 + j * 16;
                ldsm_x4(bf[j][0], bf[j][1], bf[j][2], bf[j][3],
                        sb + G_TILEB + swz(r, ks * 2 + b_s0));
            }
#pragma unroll
            for (int ma = 0; ma < 4; ++ma)
#pragma unroll
                for (int na = 0; na < 4; ++na)
                    mma16816(acc[ma][na], af[ma], bf[na >> 1][(na & 1) * 2],
                             bf[na >> 1][(na & 1) * 2 + 1]);
        }
    }

    // epilogue
#pragma unroll
    for (int ma = 0; ma < 4; ++ma) {
        const int row0 = by * 128 + warp_m * 64 + ma * 16 + (lane >> 2);
        const int row1 = row0 + 8;
#pragma unroll
        for (int na = 0; na < 4; ++na) {
            const int col = bx * 128 + warp_n * 32 + na * 8 + (lane & 3) * 2;
            float v0 = acc[ma][na][0] + bias[col];
            float v1 = acc[ma][na][1] + bias[col + 1];
            float v2 = acc[ma][na][2] + bias[col];
            float v3 = acc[ma][na][3] + bias[col + 1];
            if (EPI == 2) {
                v0 += R[(size_t)row0 * N + col];     v1 += R[(size_t)row0 * N + col + 1];
                v2 += R[(size_t)row1 * N + col];     v3 += R[(size_t)row1 * N + col + 1];
            }
            if (EPI == 3) {
                v0 = 0.5f * v0 * (1.0f + erff(v0 * 0.70710678118654752f));
                v1 = 0.5f * v1 * (1.0f + erff(v1 * 0.70710678118654752f));
                v2 = 0.5f * v2 * (1.0f + erff(v2 * 0.70710678118654752f));
                v3 = 0.5f * v3 * (1.0f + erff(v3 * 0.70710678118654752f));
                // write [hi | lo | hi] bf16 pairs into Ce [row][3N]
                __nv_bfloat162 h0, l0, h1, l1;
                h0.x = __float2bfloat16(v0); h0.y = __float2bfloat16(v1);
                l0.x = __float2bfloat16(v0 - __bfloat162float(h0.x));
                l0.y = __float2bfloat16(v1 - __bfloat162float(h0.y));
                h1.x = __float2bfloat16(v2); h1.y = __float2bfloat16(v3);
                l1.x = __float2bfloat16(v2 - __bfloat162float(h1.x));
                l1.y = __float2bfloat16(v3 - __bfloat162float(h1.y));
                __nv_bfloat16* c0 = Ce + (size_t)row0 * 3 * N;
                __nv_bfloat16* c1 = Ce + (size_t)row1 * 3 * N;
                *reinterpret_cast<__nv_bfloat162*>(c0 + col)         = h0;
                *reinterpret_cast<__nv_bfloat162*>(c0 + N + col)     = l0;
                *reinterpret_cast<__nv_bfloat162*>(c0 + 2 * N + col) = h0;
                *reinterpret_cast<__nv_bfloat162*>(c1 + col)         = h1;
                *reinterpret_cast<__nv_bfloat162*>(c1 + N + col)     = l1;
                *reinterpret_cast<__nv_bfloat162*>(c1 + 2 * N + col) = h1;
            } else {
                *reinterpret_cast<float2*>(Cf + (size_t)row0 * N + col) = make_float2(v0, v1);
                *reinterpret_cast<float2*>(Cf + (size_t)row1 * N + col) = make_float2(v2, v3);
            }
        }
    }
}

// ---------------------------------------------------------------------------
// Fused masked-causal attention over the fused qkv buffer [row][3072].
// Output: expanded bf16 [hi|lo|hi] into aexpC [row][3C].
// ---------------------------------------------------------------------------
__global__ __launch_bounds__(256)
void attn_kernel(const float* __restrict__ QKV, __nv_bfloat16* __restrict__ Ye)
{
    const int bh = blockIdx.x;
    const int b  = bh >> 4;
    const int h  = bh & 15;
    const int qbase = blockIdx.y * 8;
    const int warp = threadIdx.x >> 5;
    const int lane = threadIdx.x & 31;
    const int tq = qbase + warp;

    __shared__ float Ks[64][66];
    __shared__ float Vs[64][66];

    const size_t rq = (size_t)(b * T_SEQ + tq) * NQKV + h * HEAD_D;
    const float q0 = QKV[rq + lane * 2];
    const float q1 = QKV[rq + lane * 2 + 1];

    float m = -INFINITY, l = 0.f, acc0 = 0.f, acc1 = 0.f;
    const int smax = qbase + 7;

    for (int s0 = 0; s0 <= smax; s0 += 64) {
        const int tile = min(64, smax + 1 - s0);
        __syncthreads();
        for (int idx = threadIdx.x; idx < 64 * 64; idx += 256) {
            const int r = idx >> 6, cc = idx & 63;
            float kv = 0.f, vv = 0.f;
            if (r < tile) {
                const size_t g = (size_t)(b * T_SEQ + s0 + r) * NQKV + h * HEAD_D + cc;
                kv = QKV[g + C_DIM];
                vv = QKV[g + 2 * C_DIM];
            }
            Ks[r][cc] = kv; Vs[r][cc] = vv;
        }
        __syncthreads();

        const int send = min(tq, s0 + 63);
        for (int s = s0; s <= send; ++s) {
            if ((s & 15) == 15) continue;
            const int r = s - s0;
            float p = q0 * Ks[r][lane * 2] + q1 * Ks[r][lane * 2 + 1];
#pragma unroll
            for (int off = 16; off; off >>= 1) p += __shfl_xor_sync(~0u, p, off);
            p *= 0.125f;
            const float mnew = fmaxf(m, p);
            const float corr = __expf(m - mnew);
            const float wgt  = __expf(p - mnew);
            l    = l * corr + wgt;
            acc0 = acc0 * corr + wgt * Vs[r][lane * 2];
            acc1 = acc1 * corr + wgt * Vs[r][lane * 2 + 1];
            m = mnew;
        }
    }
    const float inv = 1.0f / l;
    const float o0 = acc0 * inv, o1 = acc1 * inv;

    const int row = b * T_SEQ + tq;
    const int c = h * HEAD_D + lane * 2;
    __nv_bfloat162 hi2, lo2;
    hi2.x = __float2bfloat16(o0); hi2.y = __float2bfloat16(o1);
    lo2.x = __float2bfloat16(o0 - __bfloat162float(hi2.x));
    lo2.y = __float2bfloat16(o1 - __bfloat162float(hi2.y));
    __nv_bfloat16* yr = Ye + (size_t)row * K3C;
    *reinterpret_cast<__nv_bfloat162*>(yr + c)             = hi2;
    *reinterpret_cast<__nv_bfloat162*>(yr + C_DIM + c)     = lo2;
    *reinterpret_cast<__nv_bfloat162*>(yr + 2 * C_DIM + c) = hi2;
}

// ---------------------------------------------------------------------------
// EinLinear head
// ---------------------------------------------------------------------------
__global__ __launch_bounds__(256)
void head_kernel(const float* __restrict__ X, const float* __restrict__ Wh,
                 float* __restrict__ out)
{
    const int e     = blockIdx.x & 15;
    const int chunk = blockIdx.x >> 4;
    const int tid = threadIdx.x;
    const int warp = tid >> 5, lane = tid & 31;

    __shared__ float xs[8][C_DIM];
    int rows[8];
#pragma unroll
    for (int j = 0; j < 8; ++j) rows[j] = (chunk * 8 + j) * TRANS + e;

#pragma unroll
    for (int j = 0; j < 8; ++j)
        for (int idx = tid; idx < C_DIM; idx += 256)
            xs[j][idx] = X[(size_t)rows[j] * C_DIM + idx];
    __syncthreads();

    for (int o = warp; o < VOCABP1; o += 8) {
        const float* w = Wh + ((size_t)e * VOCABP1 + o) * C_DIM;
        float a[8];
#pragma unroll
        for (int j = 0; j < 8; ++j) a[j] = 0.f;
        for (int k = lane; k < C_DIM; k += 32) {
            const float wv = w[k];
#pragma unroll
            for (int j = 0; j < 8; ++j) a[j] += wv * xs[j][k];
        }
#pragma unroll
        for (int j = 0; j < 8; ++j)
#pragma unroll
            for (int off = 16; off; off >>= 1)
                a[j] += __shfl_xor_sync(~0u, a[j], off);
        if (lane == 0) {
#pragma unroll
            for (int j = 0; j < 8; ++j)
                out[(size_t)rows[j] * VOCABP1 + o] = a[j];
        }
    }
}

// ---------------------------------------------------------------------------
// Launch
// ---------------------------------------------------------------------------
extern "C" void kernel_launch(void* const* d_in, const int* in_sizes, int n_in,
                              void* d_out, int out_size)
{
    const int*   tokens  = (const int*)  d_in[0];
    const float* tok_emb = (const float*)d_in[1];
    const float* pos_emb = (const float*)d_in[2];
    const float* Wq = (const float*)d_in[3];  const float* bq = (const float*)d_in[4];
    const float* Wk = (const float*)d_in[5];  const float* bk = (const float*)d_in[6];
    const float* Wv = (const float*)d_in[7];  const float* bv = (const float*)d_in[8];
    const float* Wp = (const float*)d_in[9];  const float* bp = (const float*)d_in[10];
    const float* ln1w = (const float*)d_in[11]; const float* ln1b = (const float*)d_in[12];
    const float* ln2w = (const float*)d_in[13]; const float* ln2b = (const float*)d_in[14];
    const float* W1 = (const float*)d_in[15]; const float* b1 = (const float*)d_in[16];
    const float* W2 = (const float*)d_in[17]; const float* b2 = (const float*)d_in[18];
    const float* lnfw = (const float*)d_in[19]; const float* lnfb = (const float*)d_in[20];
    const float* head_w = (const float*)d_in[21];

    float *x, *h, *qkv, *bqkv;
    __nv_bfloat16 *aC, *aF, *wqkvx, *wpx, *w1x, *w2x;
    cudaGetSymbolAddress((void**)&x,    g_x);
    cudaGetSymbolAddress((void**)&h,    g_h);
    cudaGetSymbolAddress((void**)&qkv,  g_qkv);
    cudaGetSymbolAddress((void**)&bqkv, g_bqkv);
    cudaGetSymbolAddress((void**)&aC,   g_aexpC);
    cudaGetSymbolAddress((void**)&aF,   g_aexpF);
    cudaGetSymbolAddress((void**)&wqkvx, g_wqkv);
    cudaGetSymbolAddress((void**)&wpx,  g_wp);
    cudaGetSymbolAddress((void**)&w1x,  g_w1);
    cudaGetSymbolAddress((void**)&w2x,  g_w2);

    cudaFuncSetAttribute(mma_gemm<1>, cudaFuncAttributeMaxDynamicSharedMemorySize, G_SMEM);
    cudaFuncSetAttribute(mma_gemm<2>, cudaFuncAttributeMaxDynamicSharedMemorySize, G_SMEM);
    cudaFuncSetAttribute(mma_gemm<3>, cudaFuncAttributeMaxDynamicSharedMemorySize, G_SMEM);

    // ---- weight expansion (per launch; deterministic) ----
    const dim3 wb(32, 8);
    for (int i = 0; i < N_LAYER; ++i) {
        const size_t wc = (size_t)i * C_DIM * C_DIM;
        __nv_bfloat16* wl = wqkvx + (size_t)i * NQKV * K3C;
        expand_wT<<<dim3(32, 32), wb>>>(Wq + wc, wl,                               C_DIM, C_DIM);
        expand_wT<<<dim3(32, 32), wb>>>(Wk + wc, wl + (size_t)C_DIM * K3C,         C_DIM, C_DIM);
        expand_wT<<<dim3(32, 32), wb>>>(Wv + wc, wl + (size_t)2 * C_DIM * K3C,     C_DIM, C_DIM);
        expand_wT<<<dim3(32, 32), wb>>>(Wp + wc, wpx + (size_t)i * C_DIM * K3C,    C_DIM, C_DIM);
        expand_wT<<<dim3(32, 128), wb>>>(W1 + (size_t)i * C_DIM * F4_DIM,
                                         w1x + (size_t)i * F4_DIM * K3C, C_DIM, F4_DIM);
        expand_wT<<<dim3(128, 32), wb>>>(W2 + (size_t)i * F4_DIM * C_DIM,
                                         w2x + (size_t)i * C_DIM * K3F, F4_DIM, C_DIM);
    }
    bqkv_kernel<<<N_LAYER * NQKV / 256, 256>>>(bq, bk, bv, bqkv);

    embed_kernel<<<ROWS * C_DIM / 256, 256>>>(tokens, tok_emb, pos_emb, x);

    const dim3 gQKV(NQKV   / 128, ROWS / 128);   // (24, 16)
    const dim3 gC  (C_DIM  / 128, ROWS / 128);   // (8, 16)
    const dim3 gF4 (F4_DIM / 128, ROWS / 128);   // (32, 16)

    for (int i = 0; i < N_LAYER; ++i) {
        const size_t bc = (size_t)i * C_DIM;

        ln_kernel<1><<<ROWS, 256>>>(x, ln1w + bc, ln1b + bc, nullptr, aC);
        mma_gemm<1><<<gQKV, 256, G_SMEM>>>(aC, wqkvx + (size_t)i * NQKV * K3C,
                                           bqkv + (size_t)i * NQKV, nullptr,
                                           qkv, nullptr, NQKV, K3C);

        attn_kernel<<<dim3(B_SZ * N_HEADS, T_SEQ / 8), 256>>>(qkv, aC);

        mma_gemm<2><<<gC, 256, G_SMEM>>>(aC, wpx + (size_t)i * C_DIM * K3C,
                                         bp + bc, x, x, nullptr, C_DIM, K3C);

        ln_kernel<1><<<ROWS, 256>>>(x, ln2w + bc, ln2b + bc, nullptr, aC);
        mma_gemm<3><<<gF4, 256, G_SMEM>>>(aC, w1x + (size_t)i * F4_DIM * K3C,
                                          b1 + (size_t)i * F4_DIM, nullptr,
                                          nullptr, aF, F4_DIM, K3C);

        mma_gemm<2><<<gC, 256, G_SMEM>>>(aF, w2x + (size_t)i * C_DIM * K3F,
                                         b2 + bc, x, x, nullptr, C_DIM, K3F);
    }

    ln_kernel<0><<<ROWS, 256>>>(x, lnfw, lnfb, h, nullptr);
    head_kernel<<<256, 256>>>(h, head_w, (float*)d_out);
}